// round 3
// baseline (speedup 1.0000x reference)
#include <cuda_runtime.h>
#include <cuda_bf16.h>

#define NN 4096
#define HH 500
#define DD 8
#define HEADS 5
#define G4 2000    // 4*H
#define HG 2500    // HEADS*H

// ---------------- scratch (no allocation allowed) ----------------
__device__ float g_x   [NN * HH];
__device__ float g_xn  [NN * HH];
__device__ float g_P   [NN * G4];
__device__ float g_gates[NN * G4];
__device__ float g_h   [NN * HH];
__device__ float g_c   [NN * HH];
__device__ float g_Z   [NN * HG];
__device__ float g_el  [NN * HEADS];
__device__ float g_er  [NN * HEADS];
__device__ float g_lat [NN];
__device__ float g_bias[G4];

// ---------------- SGEMM: C[M,Nn] = A[M,K] @ B[K,Nn] (+addMat)(+bias)(relu) ----
// M must be a multiple of 128 (always 4096 here). Nn, K arbitrary.
__global__ __launch_bounds__(256) void sgemm(
    const float* __restrict__ A, const float* __restrict__ B,
    float* __restrict__ C, int M, int Nn, int K,
    const float* __restrict__ addMat, int addLd,
    const int* __restrict__ gIdx, int gStride,
    const float* __restrict__ bias, int doRelu)
{
    __shared__ float As[8][128];
    __shared__ float Bs[8][128];
    const int bm = blockIdx.y * 128;
    const int bn = blockIdx.x * 128;
    const int tid = threadIdx.x;

    const int tr = (tid / 16) * 8;
    const int tc = (tid % 16) * 8;

    float acc[8][8];
#pragma unroll
    for (int i = 0; i < 8; i++)
#pragma unroll
        for (int j = 0; j < 8; j++) acc[i][j] = 0.f;

    const int arow = tid >> 1;          // 0..127
    const int acol = (tid & 1) * 4;     // 0 or 4
    const int brow = tid >> 5;          // 0..7
    const int bcol = (tid & 31) * 4;    // 0..124

    for (int k0 = 0; k0 < K; k0 += 8) {
#pragma unroll
        for (int i = 0; i < 4; i++) {
            int kk = k0 + acol + i;
            As[acol + i][arow] = (kk < K) ? A[(size_t)(bm + arow) * K + kk] : 0.f;
        }
#pragma unroll
        for (int i = 0; i < 4; i++) {
            int nn = bn + bcol + i;
            int kk = k0 + brow;
            Bs[brow][bcol + i] = (kk < K && nn < Nn) ? B[(size_t)kk * Nn + nn] : 0.f;
        }
        __syncthreads();
#pragma unroll
        for (int kk = 0; kk < 8; kk++) {
            float a[8], b[8];
#pragma unroll
            for (int i = 0; i < 8; i++) a[i] = As[kk][tr + i];
#pragma unroll
            for (int j = 0; j < 8; j++) b[j] = Bs[kk][tc + j];
#pragma unroll
            for (int i = 0; i < 8; i++)
#pragma unroll
                for (int j = 0; j < 8; j++) acc[i][j] += a[i] * b[j];
        }
        __syncthreads();
    }

#pragma unroll
    for (int i = 0; i < 8; i++) {
        int m = bm + tr + i;
        int r = m;
        if (gIdx) r = gIdx[(size_t)m * gStride];
#pragma unroll
        for (int j = 0; j < 8; j++) {
            int n = bn + tc + j;
            if (n < Nn) {
                float v = acc[i][j];
                if (addMat) v += addMat[(size_t)r * addLd + n];
                if (bias)   v += bias[n];
                if (doRelu) v = fmaxf(v, 0.f);
                C[(size_t)m * Nn + n] = v;
            }
        }
    }
}

// ---------------- small helpers ----------------
__global__ void gather_emb_k(const int* __restrict__ ids,
                             const float* __restrict__ emb,
                             float* __restrict__ x)
{
    int idx = blockIdx.x * blockDim.x + threadIdx.x;
    if (idx < NN * HH) {
        int n = idx / HH, j = idx - n * HH;
        x[idx] = emb[ids[n] * HH + j];
    }
}

__global__ void addvec_k(const float* __restrict__ a, const float* __restrict__ b,
                         float* __restrict__ o, int n)
{
    int i = blockIdx.x * blockDim.x + threadIdx.x;
    if (i < n) o[i] = a[i] + b[i];
}

// dst[m, 0..cols) = src[idx[m*stride], 0..cols)
__global__ void gather_rows_k(const float* __restrict__ src, float* __restrict__ dst,
                              const int* __restrict__ idx, int stride, int cols)
{
    int i = blockIdx.x * blockDim.x + threadIdx.x;
    if (i < NN * cols) {
        int m = i / cols, j = i - m * cols;
        dst[i] = src[(size_t)idx[(size_t)m * stride] * cols + j];
    }
}

__device__ __forceinline__ float sigm(float x) { return 1.f / (1.f + expf(-x)); }

__global__ void lstm_cell_k(const float* __restrict__ gates,
                            float* __restrict__ h, float* __restrict__ c)
{
    int idx = blockIdx.x * blockDim.x + threadIdx.x;
    if (idx < NN * HH) {
        int n = idx / HH, j = idx - n * HH;
        const float* gr = gates + (size_t)n * G4;
        float gi = gr[j], gf = gr[HH + j], gg = gr[2 * HH + j], go = gr[3 * HH + j];
        float cc = c[idx];
        cc = sigm(gf) * cc + sigm(gi) * tanhf(gg);
        h[idx] = sigm(go) * tanhf(cc);
        c[idx] = cc;
    }
}

// per (node, head) attention scores: warp per pair
__global__ void eler_k(const float* __restrict__ Z, const float* __restrict__ al,
                       const float* __restrict__ ar,
                       float* __restrict__ el, float* __restrict__ er)
{
    int pair = blockIdx.x * 8 + (threadIdx.x >> 5);
    if (pair >= NN * HEADS) return;
    int lane = threadIdx.x & 31;
    int n = pair / HEADS, h = pair - n * HEADS;
    const float* zrow = Z + (size_t)n * HG + h * HH;
    const float* alr = al + h * HH;
    const float* arr = ar + h * HH;
    float sl = 0.f, sr = 0.f;
    for (int c = lane; c < HH; c += 32) {
        float zv = zrow[c];
        sl += zv * alr[c];
        sr += zv * arr[c];
    }
#pragma unroll
    for (int o = 16; o; o >>= 1) {
        sl += __shfl_down_sync(0xffffffffu, sl, o);
        sr += __shfl_down_sync(0xffffffffu, sr, o);
    }
    if (lane == 0) { el[pair] = sl; er[pair] = sr; }
}

// GAT aggregation + relu + head-mean + elu + readout dot, fused; block per node
__global__ __launch_bounds__(128) void gat_readout_k(
    const float* __restrict__ Z, const float* __restrict__ el,
    const float* __restrict__ er, const int* __restrict__ neighbors,
    const float* __restrict__ Wr, const float* __restrict__ br,
    float* __restrict__ lat)
{
    int n = blockIdx.x;
    __shared__ int   nbr[DD];
    __shared__ float alpha[DD][HEADS];
    __shared__ float red[128];
    int tid = threadIdx.x;
    if (tid < DD) nbr[tid] = neighbors[n * DD + tid];
    __syncthreads();
    if (tid < DD * HEADS) {
        int d = tid / HEADS, h = tid - d * HEADS;
        float e = el[nbr[d] * HEADS + h] + er[n * HEADS + h];
        alpha[d][h] = (e > 0.f) ? e : 0.2f * e;   // leaky_relu
    }
    __syncthreads();
    if (tid < HEADS) {
        float mx = -1e30f;
#pragma unroll
        for (int d = 0; d < DD; d++) mx = fmaxf(mx, alpha[d][tid]);
        float ex[DD]; float s = 0.f;
#pragma unroll
        for (int d = 0; d < DD; d++) { ex[d] = expf(alpha[d][tid] - mx); s += ex[d]; }
        float inv = 1.f / s;
#pragma unroll
        for (int d = 0; d < DD; d++) alpha[d][tid] = ex[d] * inv;
    }
    __syncthreads();
    float acc = 0.f;
    for (int c = tid; c < HH; c += 128) {
        float mean = 0.f;
#pragma unroll
        for (int h = 0; h < HEADS; h++) {
            float s = 0.f;
#pragma unroll
            for (int d = 0; d < DD; d++)
                s += alpha[d][h] * Z[(size_t)nbr[d] * HG + h * HH + c];
            mean += fmaxf(s, 0.f);                // relu after GAT
        }
        mean *= (1.f / HEADS);
        float v = (mean > 0.f) ? mean : expm1f(mean);  // elu
        acc += v * Wr[c];
    }
    red[tid] = acc;
    __syncthreads();
#pragma unroll
    for (int o = 64; o; o >>= 1) {
        if (tid < o) red[tid] += red[tid + o];
        __syncthreads();
    }
    if (tid == 0) lat[n] = red[0] + br[0];
}

// deterministic segment sum: one block per graph
__global__ void segsum_k(const float* __restrict__ lat, const int* __restrict__ gid,
                         float* __restrict__ out, int n)
{
    int g = blockIdx.x, tid = threadIdx.x;
    __shared__ float red[256];
    float acc = 0.f;
    for (int i = tid; i < n; i += 256)
        if (gid[i] == g) acc += lat[i];
    red[tid] = acc;
    __syncthreads();
#pragma unroll
    for (int o = 128; o; o >>= 1) {
        if (tid < o) red[tid] += red[tid + o];
        __syncthreads();
    }
    if (tid == 0) out[g] = red[0];
}

// ---------------- host ----------------
extern "C" void kernel_launch(void* const* d_in, const int* in_sizes, int n_in,
                              void* d_out, int out_size)
{
    const int*   node_ids  = (const int*)d_in[0];
    const int*   neighbors = (const int*)d_in[1];
    const int*   graph_ids = (const int*)d_in[2];
    const float* emb       = (const float*)d_in[4];
    // per layer: Wih, Whh, bih, bhh, Wself, Wneigh, b at 5 + 7*l
    const float* Wg = (const float*)d_in[26];
    const float* al = (const float*)d_in[27];
    const float* ar = (const float*)d_in[28];
    const float* Wr = (const float*)d_in[29];
    const float* br = (const float*)d_in[30];
    float* out = (float*)d_out;

    float *x, *xn, *P, *gates, *h, *c, *Z, *el, *er, *lat, *bias;
    cudaGetSymbolAddress((void**)&x,    g_x);
    cudaGetSymbolAddress((void**)&xn,   g_xn);
    cudaGetSymbolAddress((void**)&P,    g_P);
    cudaGetSymbolAddress((void**)&gates,g_gates);
    cudaGetSymbolAddress((void**)&h,    g_h);
    cudaGetSymbolAddress((void**)&c,    g_c);
    cudaGetSymbolAddress((void**)&Z,    g_Z);
    cudaGetSymbolAddress((void**)&el,   g_el);
    cudaGetSymbolAddress((void**)&er,   g_er);
    cudaGetSymbolAddress((void**)&lat,  g_lat);
    cudaGetSymbolAddress((void**)&bias, g_bias);

    const int TPB = 256;
    gather_emb_k<<<(NN * HH + TPB - 1) / TPB, TPB>>>(node_ids, emb, x);

    for (int l = 0; l < 3; l++) {
        const float* Wih    = (const float*)d_in[5 + 7 * l + 0];
        const float* Whh    = (const float*)d_in[5 + 7 * l + 1];
        const float* bih    = (const float*)d_in[5 + 7 * l + 2];
        const float* bhh    = (const float*)d_in[5 + 7 * l + 3];
        const float* Wself  = (const float*)d_in[5 + 7 * l + 4];
        const float* Wneigh = (const float*)d_in[5 + 7 * l + 5];
        const float* b      = (const float*)d_in[5 + 7 * l + 6];

        addvec_k<<<(G4 + TPB - 1) / TPB, TPB>>>(bih, bhh, bias, G4);

        // P = x @ Wih + (bih+bhh)   [4096, 2000]
        {
            dim3 grid((G4 + 127) / 128, NN / 128);
            sgemm<<<grid, 256>>>(x, Wih, P, NN, G4, HH,
                                 nullptr, 0, nullptr, 0, bias, 0);
        }
        cudaMemsetAsync(c, 0, (size_t)NN * HH * sizeof(float));

        // t = 0: h == 0 -> gates are just gathered P rows
        gather_rows_k<<<(NN * G4 + TPB - 1) / TPB, TPB>>>(P, gates, neighbors + 0, DD, G4);
        lstm_cell_k<<<(NN * HH + TPB - 1) / TPB, TPB>>>(gates, h, c);

        for (int t = 1; t < DD; t++) {
            dim3 grid((G4 + 127) / 128, NN / 128);
            sgemm<<<grid, 256>>>(h, Whh, gates, NN, G4, HH,
                                 P, G4, neighbors + t, DD, nullptr, 0);
            lstm_cell_k<<<(NN * HH + TPB - 1) / TPB, TPB>>>(gates, h, c);
        }

        // xn = relu(x@Wself + h@Wneigh + b); use gates buffer as tmp
        {
            dim3 grid((HH + 127) / 128, NN / 128);
            sgemm<<<grid, 256>>>(x, Wself, gates, NN, HH, HH,
                                 nullptr, 0, nullptr, 0, nullptr, 0);
            sgemm<<<grid, 256>>>(h, Wneigh, xn, NN, HH, HH,
                                 gates, HH, nullptr, 0, b, 1);
        }
        float* tmpp = x; x = xn; xn = tmpp;
    }

    // GAT
    {
        dim3 grid((HG + 127) / 128, NN / 128);
        sgemm<<<grid, 256>>>(x, Wg, Z, NN, HG, HH,
                             nullptr, 0, nullptr, 0, nullptr, 0);
    }
    eler_k<<<(NN * HEADS + 7) / 8, 256>>>(Z, al, ar, el, er);
    gat_readout_k<<<NN, 128>>>(Z, el, er, neighbors, Wr, br, lat);
    segsum_k<<<out_size, 256>>>(lat, graph_ids, out, NN);
}

// round 10
// speedup vs baseline: 1.2097x; 1.2097x over previous
#include <cuda_runtime.h>

#define NN 4096
#define HH 500
#define DD 8
#define HEADS 5
#define KP 512          // padded feature block (K)
#define G4P 2048        // padded gate columns (4*HH -> 2048)
#define HGP 2560        // padded HEADS*HH (2500 -> 2560)
#define BM 128
#define BN 128
#define BK 16

typedef unsigned long long ull;

// ---------------- scratch (device globals; zero-initialized BSS) ----------------
__device__ float g_xh0[NN * 1024];   // cols [0,512): x (padded), [512,1024): h (padded)
__device__ float g_xh1[NN * 1024];
__device__ float g_c  [NN * KP];
__device__ float g_Pp [NN * G4P];    // permuted, padded P = x@Wih + bias
__device__ float g_WihP[KP * G4P];
__device__ float g_WhhP[KP * G4P];
__device__ float g_WsnP[1024 * KP];  // rows [0,500): Wself, [512,1012): Wneigh
__device__ float g_WgP [KP * HGP];
__device__ float g_biasP[G4P];
__device__ float g_bP  [KP];
__device__ float g_Z  [NN * HGP];
__device__ float g_el [NN * HEADS];
__device__ float g_er [NN * HEADS];
__device__ float g_lat[NN];

__device__ __forceinline__ float sigm(float x) { return 1.f / (1.f + expf(-x)); }

#define FMA2(acc, a, b) asm("fma.rn.f32x2 %0, %1, %2, %0;" : "+l"(acc) : "l"(a), "l"(b))

__device__ __forceinline__ float2 unpack2(ull v) {
    float2 r;
    asm("mov.b64 {%0, %1}, %2;" : "=f"(r.x), "=f"(r.y) : "l"(v));
    return r;
}

// ---------------- GEMM core: 128x128 tile, BK=16, double-buffered, FFMA2 ------
// A [M x >=K] row-major (lda), B [K x Nn] row-major (ldb). K multiple of BK.
// As2 holds A transposed AND lane-duplicated: As2[k][2m]=As2[k][2m+1]=A[m][k].
struct Frag { float4 a0, a1, b0, b1; };

__device__ __forceinline__ void g_fetch(const float* __restrict__ A, int lda,
                                        const float* __restrict__ B, int ldb,
                                        int k0, int bm, int bn,
                                        int am, int kv, int kb, int cb, Frag& f)
{
    const float* ap = A + (size_t)(bm + am) * lda + k0 + kv * 8;
    f.a0 = *(const float4*)(ap);
    f.a1 = *(const float4*)(ap + 4);
    f.b0 = *(const float4*)(B + (size_t)(k0 + kb) * ldb + bn + cb);
    f.b1 = *(const float4*)(B + (size_t)(k0 + kb + 8) * ldb + bn + cb);
}

__device__ __forceinline__ void g_stash(float As2[BK][2 * BM], float Bs[BK][BN],
                                        int am, int kv, int kb, int cb, const Frag& f)
{
    const int kbase = kv * 8;
    float va[8] = {f.a0.x, f.a0.y, f.a0.z, f.a0.w, f.a1.x, f.a1.y, f.a1.z, f.a1.w};
#pragma unroll
    for (int i = 0; i < 8; i++)
        *(float2*)&As2[kbase + i][2 * am] = make_float2(va[i], va[i]);
    *(float4*)&Bs[kb][cb] = f.b0;
    *(float4*)&Bs[kb + 8][cb] = f.b1;
}

__device__ __forceinline__ void gemm_main(
    const float* __restrict__ A, int lda,
    const float* __restrict__ B, int ldb, int K,
    float As2[2][BK][2 * BM], float Bs[2][BK][BN],
    ull acc2[8][4])
{
    const int tid = threadIdx.x;
    const int bm = blockIdx.y * BM, bn = blockIdx.x * BN;
    const int am = tid & 127, kv = tid >> 7;
    const int kb = tid >> 5, cb = (tid & 31) * 4;
    const int tr = (tid / 16) * 8, tc = (tid % 16) * 8;

    Frag f;
    g_fetch(A, lda, B, ldb, 0, bm, bn, am, kv, kb, cb, f);
    g_stash(As2[0], Bs[0], am, kv, kb, cb, f);
    __syncthreads();

    int cur = 0;
    for (int k0 = 0; k0 < K; k0 += BK) {
        const bool more = (k0 + BK) < K;
        if (more) g_fetch(A, lda, B, ldb, k0 + BK, bm, bn, am, kv, kb, cb, f);
#pragma unroll
        for (int kk = 0; kk < BK; kk++) {
            double2 bd0 = *(const double2*)&Bs[cur][kk][tc];
            double2 bd1 = *(const double2*)&Bs[cur][kk][tc + 4];
            ull b2[4] = {__double_as_longlong(bd0.x), __double_as_longlong(bd0.y),
                         __double_as_longlong(bd1.x), __double_as_longlong(bd1.y)};
            ull a2[8];
#pragma unroll
            for (int i = 0; i < 8; i++)
                a2[i] = *(const ull*)&As2[cur][kk][2 * (tr + i)];
#pragma unroll
            for (int i = 0; i < 8; i++)
#pragma unroll
                for (int jp = 0; jp < 4; jp++)
                    FMA2(acc2[i][jp], a2[i], b2[jp]);
        }
        if (more) g_stash(As2[cur ^ 1], Bs[cur ^ 1], am, kv, kb, cb, f);
        __syncthreads();
        cur ^= 1;
    }
}

// ---------------- GEMM with generic epilogue (bias + optional relu) ----------
__global__ __launch_bounds__(256, 2) void sgemm_ep_k(
    const float* __restrict__ A, int lda,
    const float* __restrict__ B, int ldb, int K,
    float* __restrict__ C, int ldc,
    const float* __restrict__ bias, int doRelu)
{
    __shared__ float As2[2][BK][2 * BM];
    __shared__ float Bs[2][BK][BN];
    ull acc2[8][4];
#pragma unroll
    for (int i = 0; i < 8; i++)
#pragma unroll
        for (int j = 0; j < 4; j++) acc2[i][j] = 0ull;

    gemm_main(A, lda, B, ldb, K, As2, Bs, acc2);

    const int tid = threadIdx.x;
    const int bm = blockIdx.y * BM, bn = blockIdx.x * BN;
    const int tr = (tid / 16) * 8, tc = (tid % 16) * 8;
#pragma unroll
    for (int i = 0; i < 8; i++) {
        const int m = bm + tr + i;
#pragma unroll
        for (int jp = 0; jp < 4; jp += 2) {
            float2 p0 = unpack2(acc2[i][jp]);
            float2 p1 = unpack2(acc2[i][jp + 1]);
            float4 v = make_float4(p0.x, p0.y, p1.x, p1.y);
            const int n = bn + tc + jp * 2;
            if (bias) {
                v.x += bias[n]; v.y += bias[n + 1];
                v.z += bias[n + 2]; v.w += bias[n + 3];
            }
            if (doRelu) {
                v.x = fmaxf(v.x, 0.f); v.y = fmaxf(v.y, 0.f);
                v.z = fmaxf(v.z, 0.f); v.w = fmaxf(v.w, 0.f);
            }
            *(float4*)&C[(size_t)m * ldc + n] = v;
        }
    }
}

// ---------------- GEMM with fused LSTM-cell epilogue (t >= 1) ----------------
// gates(m, 4j+g) = (hIn @ WhhP)(m, 4j+g) + Pp(nbr_t[m], 4j+g); apply cell.
__global__ __launch_bounds__(256, 2) void sgemm_lstm_k(
    const float* __restrict__ hIn,           // lda 1024 (xh h-region base)
    const float* __restrict__ WhhP,
    const float* __restrict__ Pp,
    const int* __restrict__ nbrT,            // neighbors + t, stride DD
    float* __restrict__ hOut,                // xh h-region base, idx m*1024 + j
    float* __restrict__ cBuf)                // idx m*KP + j
{
    __shared__ float As2[2][BK][2 * BM];
    __shared__ float Bs[2][BK][BN];
    ull acc2[8][4];
#pragma unroll
    for (int i = 0; i < 8; i++)
#pragma unroll
        for (int j = 0; j < 4; j++) acc2[i][j] = 0ull;

    gemm_main(hIn, 1024, WhhP, G4P, KP, As2, Bs, acc2);

    const int tid = threadIdx.x;
    const int bm = blockIdx.y * BM, bn = blockIdx.x * BN;
    const int tr = (tid / 16) * 8, tc = (tid % 16) * 8;
#pragma unroll
    for (int i = 0; i < 8; i++) {
        const int m = bm + tr + i;
        const int r = nbrT[m * DD];
        const float* prow = Pp + (size_t)r * G4P + bn + tc;
#pragma unroll
        for (int q = 0; q < 2; q++) {
            const int j = ((bn + tc) >> 2) + q;
            if (j < HH) {
                float4 p = *(const float4*)(prow + q * 4);
                float2 v0 = unpack2(acc2[i][q * 2]);
                float2 v1 = unpack2(acc2[i][q * 2 + 1]);
                float gi = v0.x + p.x;
                float gf = v0.y + p.y;
                float gg = v1.x + p.z;
                float go = v1.y + p.w;
                float cc = cBuf[(size_t)m * KP + j];
                cc = sigm(gf) * cc + sigm(gi) * tanhf(gg);
                cBuf[(size_t)m * KP + j] = cc;
                hOut[(size_t)m * 1024 + j] = sigm(go) * tanhf(cc);
            }
        }
    }
}

// ---------------- LSTM t=0 (h0 = c0 = 0): pure gather + cell ----------------
__global__ void lstm_t0_k(const float* __restrict__ Pp, const int* __restrict__ nbr0,
                          float* __restrict__ hOut, float* __restrict__ cBuf)
{
    int idx = blockIdx.x * blockDim.x + threadIdx.x;
    if (idx >= NN * HH) return;
    int m = idx / HH, j = idx - m * HH;
    int r = nbr0[m * DD];
    float4 p = *(const float4*)(Pp + (size_t)r * G4P + 4 * j);  // (i,f,g,o)
    float cc = sigm(p.x) * tanhf(p.z);
    cBuf[(size_t)m * KP + j] = cc;
    hOut[(size_t)m * 1024 + j] = sigm(p.w) * tanhf(cc);
}

// ---------------- weight prep kernels ----------------
// Wp[k][4j+g] = W[k][g*HH + j] (zero-padded to KP x G4P)
__global__ void permW_k(const float* __restrict__ W, float* __restrict__ Wp)
{
    int idx = blockIdx.x * blockDim.x + threadIdx.x;
    if (idx >= KP * G4P) return;
    int k = idx / G4P, c = idx - k * G4P;
    int j = c >> 2, g = c & 3;
    float v = 0.f;
    if (k < HH && j < HH) v = W[k * (4 * HH) + g * HH + j];
    Wp[idx] = v;
}

__global__ void biasperm_k(const float* __restrict__ bih, const float* __restrict__ bhh,
                           float* __restrict__ biasP,
                           const float* __restrict__ b, float* __restrict__ bP)
{
    int idx = blockIdx.x * blockDim.x + threadIdx.x;
    if (idx < G4P) {
        int j = idx >> 2, g = idx & 3;
        biasP[idx] = (j < HH) ? (bih[g * HH + j] + bhh[g * HH + j]) : 0.f;
    }
    if (idx < KP) bP[idx] = (idx < HH) ? b[idx] : 0.f;
}

__global__ void padWsn_k(const float* __restrict__ Wself, const float* __restrict__ Wneigh,
                         float* __restrict__ Wp)
{
    int idx = blockIdx.x * blockDim.x + threadIdx.x;
    if (idx >= 1024 * KP) return;
    int k = idx / KP, n = idx - k * KP;
    float v = 0.f;
    if (n < HH) {
        if (k < HH) v = Wself[k * HH + n];
        else if (k >= 512 && k < 512 + HH) v = Wneigh[(k - 512) * HH + n];
    }
    Wp[idx] = v;
}

__global__ void padWg_k(const float* __restrict__ Wg, float* __restrict__ Wp)
{
    int idx = blockIdx.x * blockDim.x + threadIdx.x;
    if (idx >= KP * HGP) return;
    int k = idx / HGP, n = idx - k * HGP;
    Wp[idx] = (k < HH && n < HEADS * HH) ? Wg[k * (HEADS * HH) + n] : 0.f;
}

// ---------------- misc ----------------
__global__ void gather_emb2_k(const int* __restrict__ ids, const float* __restrict__ emb,
                              float* __restrict__ xh)
{
    int idx = blockIdx.x * blockDim.x + threadIdx.x;
    if (idx >= NN * KP) return;
    int m = idx / KP, j = idx - m * KP;
    xh[(size_t)m * 1024 + j] = (j < HH) ? emb[ids[m] * HH + j] : 0.f;
}

// per (node, head) attention scores: warp per pair
__global__ void eler_k(const float* __restrict__ Z, const float* __restrict__ al,
                       const float* __restrict__ ar,
                       float* __restrict__ el, float* __restrict__ er)
{
    int pair = blockIdx.x * 8 + (threadIdx.x >> 5);
    if (pair >= NN * HEADS) return;
    int lane = threadIdx.x & 31;
    int n = pair / HEADS, h = pair - n * HEADS;
    const float* zrow = Z + (size_t)n * HGP + h * HH;
    const float* alr = al + h * HH;
    const float* arr = ar + h * HH;
    float sl = 0.f, sr = 0.f;
    for (int c = lane; c < HH; c += 32) {
        float zv = zrow[c];
        sl += zv * alr[c];
        sr += zv * arr[c];
    }
#pragma unroll
    for (int o = 16; o; o >>= 1) {
        sl += __shfl_down_sync(0xffffffffu, sl, o);
        sr += __shfl_down_sync(0xffffffffu, sr, o);
    }
    if (lane == 0) { el[pair] = sl; er[pair] = sr; }
}

// GAT aggregation + relu + head-mean + elu + readout dot, fused; block per node
__global__ __launch_bounds__(128) void gat_readout_k(
    const float* __restrict__ Z, const float* __restrict__ el,
    const float* __restrict__ er, const int* __restrict__ neighbors,
    const float* __restrict__ Wr, const float* __restrict__ br,
    float* __restrict__ lat)
{
    int n = blockIdx.x;
    __shared__ int   nbr[DD];
    __shared__ float alpha[DD][HEADS];
    __shared__ float red[128];
    int tid = threadIdx.x;
    if (tid < DD) nbr[tid] = neighbors[n * DD + tid];
    __syncthreads();
    if (tid < DD * HEADS) {
        int d = tid / HEADS, h = tid - d * HEADS;
        float e = el[nbr[d] * HEADS + h] + er[n * HEADS + h];
        alpha[d][h] = (e > 0.f) ? e : 0.2f * e;   // leaky_relu
    }
    __syncthreads();
    if (tid < HEADS) {
        float mx = -1e30f;
#pragma unroll
        for (int d = 0; d < DD; d++) mx = fmaxf(mx, alpha[d][tid]);
        float ex[DD]; float s = 0.f;
#pragma unroll
        for (int d = 0; d < DD; d++) { ex[d] = expf(alpha[d][tid] - mx); s += ex[d]; }
        float inv = 1.f / s;
#pragma unroll
        for (int d = 0; d < DD; d++) alpha[d][tid] = ex[d] * inv;
    }
    __syncthreads();
    float acc = 0.f;
    for (int c = tid; c < HH; c += 128) {
        float mean = 0.f;
#pragma unroll
        for (int h = 0; h < HEADS; h++) {
            float s = 0.f;
#pragma unroll
            for (int d = 0; d < DD; d++)
                s += alpha[d][h] * Z[(size_t)nbr[d] * HGP + h * HH + c];
            mean += fmaxf(s, 0.f);                // relu after GAT
        }
        mean *= (1.f / HEADS);
        float v = (mean > 0.f) ? mean : expm1f(mean);  // elu
        acc += v * Wr[c];
    }
    red[tid] = acc;
    __syncthreads();
#pragma unroll
    for (int o = 64; o; o >>= 1) {
        if (tid < o) red[tid] += red[tid + o];
        __syncthreads();
    }
    if (tid == 0) lat[n] = red[0] + br[0];
}

// deterministic segment sum: one block per graph
__global__ void segsum_k(const float* __restrict__ lat, const int* __restrict__ gid,
                         float* __restrict__ out, int n)
{
    int g = blockIdx.x, tid = threadIdx.x;
    __shared__ float red[256];
    float acc = 0.f;
    for (int i = tid; i < n; i += 256)
        if (gid[i] == g) acc += lat[i];
    red[tid] = acc;
    __syncthreads();
#pragma unroll
    for (int o = 128; o; o >>= 1) {
        if (tid < o) red[tid] += red[tid + o];
        __syncthreads();
    }
    if (tid == 0) out[g] = red[0];
}

// ---------------- host ----------------
extern "C" void kernel_launch(void* const* d_in, const int* in_sizes, int n_in,
                              void* d_out, int out_size)
{
    const int*   node_ids  = (const int*)d_in[0];
    const int*   neighbors = (const int*)d_in[1];
    const int*   graph_ids = (const int*)d_in[2];
    const float* emb       = (const float*)d_in[4];
    const float* Wg = (const float*)d_in[26];
    const float* al = (const float*)d_in[27];
    const float* ar = (const float*)d_in[28];
    const float* Wr = (const float*)d_in[29];
    const float* br = (const float*)d_in[30];
    float* out = (float*)d_out;

    float *xh0, *xh1, *cB, *Pp, *WihP, *WhhP, *WsnP, *WgP, *biasP, *bP, *Z, *el, *er, *lat;
    cudaGetSymbolAddress((void**)&xh0,  g_xh0);
    cudaGetSymbolAddress((void**)&xh1,  g_xh1);
    cudaGetSymbolAddress((void**)&cB,   g_c);
    cudaGetSymbolAddress((void**)&Pp,   g_Pp);
    cudaGetSymbolAddress((void**)&WihP, g_WihP);
    cudaGetSymbolAddress((void**)&WhhP, g_WhhP);
    cudaGetSymbolAddress((void**)&WsnP, g_WsnP);
    cudaGetSymbolAddress((void**)&WgP,  g_WgP);
    cudaGetSymbolAddress((void**)&biasP,g_biasP);
    cudaGetSymbolAddress((void**)&bP,   g_bP);
    cudaGetSymbolAddress((void**)&Z,    g_Z);
    cudaGetSymbolAddress((void**)&el,   g_el);
    cudaGetSymbolAddress((void**)&er,   g_er);
    cudaGetSymbolAddress((void**)&lat,  g_lat);

    float* xh[2] = {xh0, xh1};
    const int TPB = 256;

    gather_emb2_k<<<(NN * KP + TPB - 1) / TPB, TPB>>>(node_ids, emb, xh[0]);
    padWg_k<<<(KP * HGP + TPB - 1) / TPB, TPB>>>(Wg, WgP);

    for (int l = 0; l < 3; l++) {
        const float* Wih    = (const float*)d_in[5 + 7 * l + 0];
        const float* Whh    = (const float*)d_in[5 + 7 * l + 1];
        const float* bih    = (const float*)d_in[5 + 7 * l + 2];
        const float* bhh    = (const float*)d_in[5 + 7 * l + 3];
        const float* Wself  = (const float*)d_in[5 + 7 * l + 4];
        const float* Wneigh = (const float*)d_in[5 + 7 * l + 5];
        const float* b      = (const float*)d_in[5 + 7 * l + 6];

        float* cur = xh[l & 1];
        float* nxt = xh[(l + 1) & 1];

        permW_k<<<(KP * G4P + TPB - 1) / TPB, TPB>>>(Wih, WihP);
        permW_k<<<(KP * G4P + TPB - 1) / TPB, TPB>>>(Whh, WhhP);
        biasperm_k<<<(G4P + TPB - 1) / TPB, TPB>>>(bih, bhh, biasP, b, bP);
        padWsn_k<<<(1024 * KP + TPB - 1) / TPB, TPB>>>(Wself, Wneigh, WsnP);

        // Pp = x @ WihP + biasP    [NN x G4P], K = KP
        {
            dim3 grid(G4P / BN, NN / BM);
            sgemm_ep_k<<<grid, 256>>>(cur, 1024, WihP, G4P, KP, Pp, G4P, biasP, 0);
        }

        // h ping-pong between the two xh buffers' h-regions; ends in cur after t=7
        float* hb[2] = {nxt + 512, cur + 512};
        lstm_t0_k<<<(NN * HH + TPB - 1) / TPB, TPB>>>(Pp, neighbors, hb[0], cB);

        for (int t = 1; t < DD; t++) {
            dim3 grid(G4P / BN, NN / BM);
            sgemm_lstm_k<<<grid, 256>>>(hb[(t + 1) & 1], WhhP, Pp,
                                        neighbors + t, hb[t & 1], cB);
        }

        // nxt.x = relu([x|h] @ WsnP + bP)  (h final is in cur+512 -> contiguous A)
        {
            dim3 grid(KP / BN, NN / BM);
            sgemm_ep_k<<<grid, 256>>>(cur, 1024, WsnP, KP, 1024, nxt, 1024, bP, 1);
        }
    }

    // Z = x @ WgP   (final x lives in xh[1])
    {
        dim3 grid(HGP / BN, NN / BM);
        sgemm_ep_k<<<grid, 256>>>(xh[1], 1024, WgP, HGP, KP, Z, HGP, (const float*)0, 0);
    }
    eler_k<<<(NN * HEADS + 7) / 8, 256>>>(Z, al, ar, el, er);
    gat_readout_k<<<NN, 128>>>(Z, el, er, neighbors, Wr, br, lat);
    segsum_k<<<out_size, 256>>>(lat, graph_ids, out, NN);
}